// round 12
// baseline (speedup 1.0000x reference)
#include <cuda_runtime.h>
#include <cuda_fp16.h>
#include <cstdint>

// ============================================================================
// Problem dims (fixed by setup_inputs)
// ============================================================================
#define DIN    2048
#define DOUT   2048
#define MROWS  8192        // B*S = 4*2048
#define GROUPS 64          // DIN/32

// ============================================================================
// Scratch (device globals; no allocation allowed)
// ============================================================================
__device__ __half g_xq[(size_t)MROWS * DIN];   // quantized x as exact integers in fp16
__device__ __half g_wh[(size_t)DOUT * DIN];    // dequantized weights in fp16
__device__ float  g_xscale[MROWS];             // per-token scale

// ============================================================================
// Portable PTX helpers (sm_80-level only: cp.async, ldmatrix, mma.sync)
// ============================================================================
__device__ __forceinline__ uint32_t smem_to_u32(const void* smem_ptr) {
    uint32_t addr;
    asm("{ .reg .u64 tmp; cvta.to.shared.u64 tmp, %1; cvt.u32.u64 %0, tmp; }"
        : "=r"(addr) : "l"(smem_ptr));
    return addr;
}

__device__ __forceinline__ void cp_async16(uint32_t smem_addr, const void* gptr) {
    asm volatile("cp.async.cg.shared.global [%0], [%1], 16;"
                 :: "r"(smem_addr), "l"(gptr));
}

template <int N>
__device__ __forceinline__ void cp_wait() {
    asm volatile("cp.async.wait_group %0;" :: "n"(N) : "memory");
}

__device__ __forceinline__ void ldsm_x4(uint32_t* r, uint32_t addr) {
    asm volatile("ldmatrix.sync.aligned.m8n8.x4.shared.b16 {%0,%1,%2,%3}, [%4];"
                 : "=r"(r[0]), "=r"(r[1]), "=r"(r[2]), "=r"(r[3])
                 : "r"(addr));
}

// f16-accumulate MMA: D(f16x2 x2) = A*B + C, C=D. 2x issue rate vs f32-acc
// if sm_103 halves the legacy fp32-accumulate path.
__device__ __forceinline__ void mma16816_f16(uint32_t* c, const uint32_t* a,
                                             uint32_t b0, uint32_t b1) {
    asm volatile(
        "mma.sync.aligned.m16n8k16.row.col.f16.f16.f16.f16 "
        "{%0,%1}, {%2,%3,%4,%5}, {%6,%7}, {%0,%1};"
        : "+r"(c[0]), "+r"(c[1])
        : "r"(a[0]), "r"(a[1]), "r"(a[2]), "r"(a[3]), "r"(b0), "r"(b1));
}

// ============================================================================
// Kernel 1 (merged prep): blocks [0, MROWS) quantize x rows; blocks
// [MROWS, MROWS+4096) dequantize W chunks.
// ============================================================================
__global__ void __launch_bounds__(256)
prep_kernel(const float* __restrict__ x,
            const int* __restrict__ wi,
            const float* __restrict__ ws,
            const float* __restrict__ wz) {
    __shared__ float red[18];
    const int tid = threadIdx.x;

    if (blockIdx.x < MROWS) {
        // ---- per-token asymmetric int8 fake-quant of x ----
        const int row = blockIdx.x;
        const float4* xr = (const float4*)(x + (size_t)row * DIN);
        float4 v0 = xr[tid];
        float4 v1 = xr[tid + 256];

        float mn = 0.0f, mx = 0.0f;   // reference min/max include 0
        mn = fminf(mn, fminf(fminf(v0.x, v0.y), fminf(v0.z, v0.w)));
        mn = fminf(mn, fminf(fminf(v1.x, v1.y), fminf(v1.z, v1.w)));
        mx = fmaxf(mx, fmaxf(fmaxf(v0.x, v0.y), fmaxf(v0.z, v0.w)));
        mx = fmaxf(mx, fmaxf(fmaxf(v1.x, v1.y), fmaxf(v1.z, v1.w)));

        #pragma unroll
        for (int off = 16; off > 0; off >>= 1) {
            mn = fminf(mn, __shfl_xor_sync(0xffffffffu, mn, off));
            mx = fmaxf(mx, __shfl_xor_sync(0xffffffffu, mx, off));
        }
        if ((tid & 31) == 0) { red[tid >> 5] = mn; red[8 + (tid >> 5)] = mx; }
        __syncthreads();
        if (tid == 0) {
            float m1 = red[0], m2 = red[8];
            #pragma unroll
            for (int w = 1; w < 8; w++) {
                m1 = fminf(m1, red[w]);
                m2 = fmaxf(m2, red[8 + w]);
            }
            float scale = fmaxf(__fdiv_rn(m2 - m1, 255.0f), 1.1920929e-07f);
            float zpf = -128.0f - rintf(__fdiv_rn(m1, scale));
            zpf = fminf(fmaxf(zpf, -128.0f), 127.0f);
            red[16] = __frcp_rn(scale);   // per-element uses reciprocal-mul
            red[17] = zpf;
            g_xscale[row] = scale;
        }
        __syncthreads();
        const float rs  = red[16];
        const float zpf = red[17];

        // q = clip(rint(x/s) + zp) - zp : integer in [-255,255], exact in fp16
        auto qd = [&](float xv) -> float {
            float q = rintf(xv * rs) + zpf;
            q = fminf(fmaxf(q, -128.0f), 127.0f);
            return q - zpf;
        };

        __half2* xq2 = (__half2*)(g_xq + (size_t)row * DIN);
        xq2[2 * tid]             = __floats2half2_rn(qd(v0.x), qd(v0.y));
        xq2[2 * tid + 1]         = __floats2half2_rn(qd(v0.z), qd(v0.w));
        xq2[2 * (tid + 256)]     = __floats2half2_rn(qd(v1.x), qd(v1.y));
        xq2[2 * (tid + 256) + 1] = __floats2half2_rn(qd(v1.z), qd(v1.w));
    } else {
        // ---- grouped-int4 dequant of W into fp16 ----
        const int idx = (blockIdx.x - MROWS) * 256 + tid;   // one int4 vec
        const int4 w4 = ((const int4*)wi)[idx];
        const int base = idx << 2;
        const int o = base >> 11;                 // / DIN
        const int g = (base & (DIN - 1)) >> 5;    // group of 32
        const float s = ws[o * GROUPS + g];
        const float z = wz[o * GROUPS + g];
        __half2 h01 = __floats2half2_rn(((float)w4.x - z) * s, ((float)w4.y - z) * s);
        __half2 h23 = __floats2half2_rn(((float)w4.z - z) * s, ((float)w4.w - z) * s);
        __half2* dst = (__half2*)(g_wh + base);
        dst[0] = h01;
        dst[1] = h23;
    }
}

// ============================================================================
// Kernel 2: fp16 mma.sync GEMM (NT), CTA 128x128, warp tile 32x64, BK=64,
// 3-stage cp.async pipeline, one barrier per iter, 2 CTAs/SM.
// f16-accumulate MMAs over a window of one BK iter (K=64), promoted to fp32
// master accumulators once per iter (4 cvt + 4 FADD per 16x16 tile).
//   out[m, n] = g_xscale[m] * sum_k g_xq[m,k] * g_wh[n,k]
//
// SMEM rows: 64 fp16 data + 8 fp16 pad = 144B stride (conflict-free ldmatrix;
// 16B-aligned cp.async chunks).
// ============================================================================
static constexpr int BM = 128;
static constexpr int BN = 128;
static constexpr int BK = 64;
static constexpr int KITERS = DIN / BK;            // 32
static constexpr int SROWB = 144;                  // bytes per smem row
static constexpr int TILE_B = 128 * SROWB;         // 18432 per operand
static constexpr int STAGE_B = 2 * TILE_B;         // 36864 (A + B)
static constexpr int NSTAGES = 3;
static constexpr int GEMM_SMEM = NSTAGES * STAGE_B;  // 110592; x2 CTAs = 221KB

__global__ void __launch_bounds__(256, 2)
qgemm_kernel(float* __restrict__ out) {
    extern __shared__ char sm[];
    const uint32_t sbase = smem_to_u32(sm);
    const int tid  = threadIdx.x;
    const int lane = tid & 31;
    const int wid  = tid >> 5;
    const int warp_m = wid & 3;    // 4 m-tiles of 32 rows
    const int warp_n = wid >> 2;   // 2 n-tiles of 64 cols
    const int n0 = blockIdx.x * BN;
    const int m0 = blockIdx.y * BM;

    const __half* ga = g_xq + (size_t)m0 * DIN;
    const __half* gb = g_wh + (size_t)n0 * DIN;

    auto load_stage = [&](int s, int k0) {
        const uint32_t abase = sbase + (uint32_t)s * STAGE_B;
        const uint32_t bbase = abase + (uint32_t)TILE_B;
        #pragma unroll
        for (int it = 0; it < 4; it++) {
            int c = tid + it * 256;          // 0..1023, one 16B chunk each
            int r = c >> 3;                  // row 0..127
            int colh = (c & 7) * 8;          // column in halves
            uint32_t soff = (uint32_t)(r * SROWB + colh * 2);
            cp_async16(abase + soff, ga + (size_t)r * DIN + k0 + colh);
            cp_async16(bbase + soff, gb + (size_t)r * DIN + k0 + colh);
        }
        asm volatile("cp.async.commit_group;" ::: "memory");
    };

    // fp32 master accumulators
    float acc[2][8][4];
    #pragma unroll
    for (int mi = 0; mi < 2; mi++)
        #pragma unroll
        for (int p = 0; p < 8; p++)
            #pragma unroll
            for (int j = 0; j < 4; j++)
                acc[mi][p][j] = 0.0f;

    load_stage(0, 0);
    load_stage(1, BK);

    // ldmatrix lane addressing: lanes 0-15 -> rows, lanes 16-31 -> +16B in k
    const uint32_t lrow = (uint32_t)(lane & 15);
    const uint32_t lkof = (uint32_t)((lane >> 4) * 16);   // bytes

    int sc = 0;
    for (int i = 0; i < KITERS; i++) {
        if (i + 2 < KITERS) cp_wait<1>(); else cp_wait<0>();
        __syncthreads();
        if (i + 2 < KITERS) {
            int sl = sc + 2; if (sl >= NSTAGES) sl -= NSTAGES;
            load_stage(sl, (i + 2) * BK);
        }

        const uint32_t abase = sbase + (uint32_t)sc * STAGE_B;
        const uint32_t bbase = abase + (uint32_t)TILE_B;
        const uint32_t arow0 = abase + (uint32_t)(warp_m * 32 + lrow) * SROWB + lkof;
        const uint32_t brow0 = bbase + (uint32_t)(warp_n * 64 + lrow) * SROWB + lkof;

        // f16 window accumulators for this BK iter (packed half2 pairs)
        uint32_t win[2][8][2];
        #pragma unroll
        for (int mi = 0; mi < 2; mi++)
            #pragma unroll
            for (int p = 0; p < 8; p++)
                win[mi][p][0] = win[mi][p][1] = 0u;

        #pragma unroll
        for (int ka = 0; ka < 4; ka++) {
            const uint32_t kb = (uint32_t)(ka * 32);   // 16 halves per k-step

            uint32_t a[2][4];
            ldsm_x4(a[0], arow0 + kb);
            ldsm_x4(a[1], arow0 + 16u * SROWB + kb);

            uint32_t bq[4][4];
            #pragma unroll
            for (int t = 0; t < 4; t++)
                ldsm_x4(bq[t], brow0 + (uint32_t)(t * 16) * SROWB + kb);

            #pragma unroll
            for (int mi = 0; mi < 2; mi++) {
                #pragma unroll
                for (int t = 0; t < 4; t++) {
                    // x4 B load t covers n-atoms 2t (regs 0,2) and 2t+1 (1,3)
                    mma16816_f16(win[mi][2 * t],     a[mi], bq[t][0], bq[t][2]);
                    mma16816_f16(win[mi][2 * t + 1], a[mi], bq[t][1], bq[t][3]);
                }
            }
        }

        // Promote f16 window into fp32 master accumulators.
        #pragma unroll
        for (int mi = 0; mi < 2; mi++) {
            #pragma unroll
            for (int p = 0; p < 8; p++) {
                float2 f0 = __half22float2(*(__half2*)&win[mi][p][0]);
                float2 f1 = __half22float2(*(__half2*)&win[mi][p][1]);
                acc[mi][p][0] += f0.x;
                acc[mi][p][1] += f0.y;
                acc[mi][p][2] += f1.x;
                acc[mi][p][3] += f1.y;
            }
        }

        sc++; if (sc == NSTAGES) sc = 0;
    }

    // Epilogue: scale by per-token scale, store fp32.
    const int qrow = lane >> 2;          // 0..7
    const int qcol = (lane & 3) * 2;     // 0,2,4,6
    #pragma unroll
    for (int mi = 0; mi < 2; mi++) {
        const int mrow0 = m0 + warp_m * 32 + mi * 16 + qrow;
        const float sc0 = g_xscale[mrow0];
        const float sc1 = g_xscale[mrow0 + 8];
        float* o0 = out + (size_t)mrow0 * DOUT + n0 + warp_n * 64 + qcol;
        float* o1 = o0 + (size_t)8 * DOUT;
        #pragma unroll
        for (int p = 0; p < 8; p++) {
            *(float2*)(o0 + p * 8) = make_float2(sc0 * acc[mi][p][0],
                                                 sc0 * acc[mi][p][1]);
            *(float2*)(o1 + p * 8) = make_float2(sc1 * acc[mi][p][2],
                                                 sc1 * acc[mi][p][3]);
        }
    }
}

// ============================================================================
// Launch
// ============================================================================
extern "C" void kernel_launch(void* const* d_in, const int* in_sizes, int n_in,
                              void* d_out, int out_size) {
    (void)in_sizes; (void)n_in; (void)out_size;
    const float* x  = (const float*)d_in[0];
    const int*   wi = (const int*)d_in[1];
    const float* ws = (const float*)d_in[2];
    const float* wz = (const float*)d_in[3];
    float* out = (float*)d_out;

    cudaFuncSetAttribute(qgemm_kernel,
                         cudaFuncAttributeMaxDynamicSharedMemorySize, GEMM_SMEM);

    prep_kernel<<<MROWS + (DOUT * DIN) / 1024, 256>>>(x, wi, ws, wz);
    qgemm_kernel<<<dim3(DOUT / BN, MROWS / BM), 256, GEMM_SMEM>>>(out);
}

// round 13
// speedup vs baseline: 1.1232x; 1.1232x over previous
#include <cuda_runtime.h>
#include <cuda_fp16.h>
#include <cstdint>

// ============================================================================
// Problem dims (fixed by setup_inputs)
// ============================================================================
#define DIN    2048
#define DOUT   2048
#define MROWS  8192        // B*S = 4*2048
#define GROUPS 64          // DIN/32

// ============================================================================
// Scratch (device globals; no allocation allowed)
// ============================================================================
__device__ __half g_xq[(size_t)MROWS * DIN];   // quantized x as exact integers in fp16
__device__ __half g_wh[(size_t)DOUT * DIN];    // dequantized weights in fp16
__device__ float  g_xscale[MROWS];             // per-token scale

// ============================================================================
// Portable PTX helpers (sm_80-level only: cp.async, ldmatrix, mma.sync)
// ============================================================================
__device__ __forceinline__ uint32_t smem_to_u32(const void* smem_ptr) {
    uint32_t addr;
    asm("{ .reg .u64 tmp; cvta.to.shared.u64 tmp, %1; cvt.u32.u64 %0, tmp; }"
        : "=r"(addr) : "l"(smem_ptr));
    return addr;
}

__device__ __forceinline__ void cp_async16(uint32_t smem_addr, const void* gptr) {
    asm volatile("cp.async.cg.shared.global [%0], [%1], 16;"
                 :: "r"(smem_addr), "l"(gptr));
}

template <int N>
__device__ __forceinline__ void cp_wait() {
    asm volatile("cp.async.wait_group %0;" :: "n"(N) : "memory");
}

__device__ __forceinline__ void ldsm_x4(uint32_t* r, uint32_t addr) {
    asm volatile("ldmatrix.sync.aligned.m8n8.x4.shared.b16 {%0,%1,%2,%3}, [%4];"
                 : "=r"(r[0]), "=r"(r[1]), "=r"(r[2]), "=r"(r[3])
                 : "r"(addr));
}

__device__ __forceinline__ void mma16816(float* d, const uint32_t* a,
                                         uint32_t b0, uint32_t b1) {
    asm volatile(
        "mma.sync.aligned.m16n8k16.row.col.f32.f16.f16.f32 "
        "{%0,%1,%2,%3}, {%4,%5,%6,%7}, {%8,%9}, {%0,%1,%2,%3};"
        : "+f"(d[0]), "+f"(d[1]), "+f"(d[2]), "+f"(d[3])
        : "r"(a[0]), "r"(a[1]), "r"(a[2]), "r"(a[3]), "r"(b0), "r"(b1));
}

// ============================================================================
// Kernel 1 (merged prep): blocks [0, MROWS) quantize x rows (one row/block,
// 8 contiguous elements per thread, single STG.128 out); blocks
// [MROWS, MROWS+2048) dequantize W (8 elements per thread).
// ============================================================================
__global__ void __launch_bounds__(256)
prep_kernel(const float* __restrict__ x,
            const int* __restrict__ wi,
            const float* __restrict__ ws,
            const float* __restrict__ wz) {
    __shared__ float red[18];
    const int tid = threadIdx.x;

    if (blockIdx.x < MROWS) {
        // ---- per-token asymmetric int8 fake-quant of x ----
        const int row = blockIdx.x;
        const float4* xr = (const float4*)(x + (size_t)row * DIN);
        // thread t owns elements [8t, 8t+8)
        float4 v0 = xr[2 * tid];
        float4 v1 = xr[2 * tid + 1];

        float mn = 0.0f, mx = 0.0f;   // reference min/max include 0
        mn = fminf(mn, fminf(fminf(v0.x, v0.y), fminf(v0.z, v0.w)));
        mn = fminf(mn, fminf(fminf(v1.x, v1.y), fminf(v1.z, v1.w)));
        mx = fmaxf(mx, fmaxf(fmaxf(v0.x, v0.y), fmaxf(v0.z, v0.w)));
        mx = fmaxf(mx, fmaxf(fmaxf(v1.x, v1.y), fmaxf(v1.z, v1.w)));

        #pragma unroll
        for (int off = 16; off > 0; off >>= 1) {
            mn = fminf(mn, __shfl_xor_sync(0xffffffffu, mn, off));
            mx = fmaxf(mx, __shfl_xor_sync(0xffffffffu, mx, off));
        }
        if ((tid & 31) == 0) { red[tid >> 5] = mn; red[8 + (tid >> 5)] = mx; }
        __syncthreads();
        if (tid == 0) {
            float m1 = red[0], m2 = red[8];
            #pragma unroll
            for (int w = 1; w < 8; w++) {
                m1 = fminf(m1, red[w]);
                m2 = fmaxf(m2, red[8 + w]);
            }
            float scale = fmaxf(__fdiv_rn(m2 - m1, 255.0f), 1.1920929e-07f);
            float zpf = -128.0f - rintf(__fdiv_rn(m1, scale));
            zpf = fminf(fmaxf(zpf, -128.0f), 127.0f);
            red[16] = __frcp_rn(scale);   // per-element uses reciprocal-mul
            red[17] = zpf;
            g_xscale[row] = scale;
        }
        __syncthreads();
        const float rs  = red[16];
        const float zpf = red[17];

        // q = clip(rint(x/s) + zp) - zp : integer in [-255,255], exact in fp16
        auto qd = [&](float xv) -> float {
            float q = rintf(xv * rs) + zpf;
            q = fminf(fmaxf(q, -128.0f), 127.0f);
            return q - zpf;
        };

        uint4 pk;
        __half2 h;
        h = __floats2half2_rn(qd(v0.x), qd(v0.y)); pk.x = *(uint32_t*)&h;
        h = __floats2half2_rn(qd(v0.z), qd(v0.w)); pk.y = *(uint32_t*)&h;
        h = __floats2half2_rn(qd(v1.x), qd(v1.y)); pk.z = *(uint32_t*)&h;
        h = __floats2half2_rn(qd(v1.z), qd(v1.w)); pk.w = *(uint32_t*)&h;
        ((uint4*)(g_xq + (size_t)row * DIN))[tid] = pk;
    } else {
        // ---- grouped-int4 dequant of W into fp16 (8 elements/thread) ----
        const int t = (blockIdx.x - MROWS) * 256 + tid;   // 8-element chunk id
        const int4* wrow = (const int4*)wi;
        const int4 wa = wrow[2 * t];
        const int4 wb = wrow[2 * t + 1];
        const int base = t << 3;
        const int o = base >> 11;                 // / DIN
        const int g = (base & (DIN - 1)) >> 5;    // group of 32 (8 aligned inside)
        const float s = ws[o * GROUPS + g];
        const float z = wz[o * GROUPS + g];
        uint4 pk;
        __half2 h;
        h = __floats2half2_rn(((float)wa.x - z) * s, ((float)wa.y - z) * s); pk.x = *(uint32_t*)&h;
        h = __floats2half2_rn(((float)wa.z - z) * s, ((float)wa.w - z) * s); pk.y = *(uint32_t*)&h;
        h = __floats2half2_rn(((float)wb.x - z) * s, ((float)wb.y - z) * s); pk.z = *(uint32_t*)&h;
        h = __floats2half2_rn(((float)wb.z - z) * s, ((float)wb.w - z) * s); pk.w = *(uint32_t*)&h;
        ((uint4*)g_wh)[t] = pk;
    }
}

// ============================================================================
// Kernel 2: fp16 mma.sync GEMM (NT), CTA 128x128, warp tile 32x64, BK=64,
// 3-stage cp.async pipeline (prefetch distance 2), one barrier per iter,
// 2 CTAs/SM, register-double-buffered fragments. (Best config: R10, 217us —
// at the legacy HMMA issue-rate ceiling, rt ~= 15.33 cyc/SMSP.)
//   out[m, n] = g_xscale[m] * sum_k g_xq[m,k] * g_wh[n,k]
//
// SMEM rows: 64 fp16 data + 8 fp16 pad = 144B stride (conflict-free ldmatrix;
// 16B-aligned cp.async chunks).
// ============================================================================
static constexpr int BM = 128;
static constexpr int BN = 128;
static constexpr int BK = 64;
static constexpr int KITERS = DIN / BK;            // 32
static constexpr int SROWB = 144;                  // bytes per smem row
static constexpr int TILE_B = 128 * SROWB;         // 18432 per operand
static constexpr int STAGE_B = 2 * TILE_B;         // 36864 (A + B)
static constexpr int NSTAGES = 3;
static constexpr int GEMM_SMEM = NSTAGES * STAGE_B;  // 110592; x2 CTAs = 221KB

__global__ void __launch_bounds__(256, 2)
qgemm_kernel(float* __restrict__ out) {
    extern __shared__ char sm[];
    const uint32_t sbase = smem_to_u32(sm);
    const int tid  = threadIdx.x;
    const int lane = tid & 31;
    const int wid  = tid >> 5;
    const int warp_m = wid & 3;    // 4 m-tiles of 32 rows
    const int warp_n = wid >> 2;   // 2 n-tiles of 64 cols
    const int n0 = blockIdx.x * BN;
    const int m0 = blockIdx.y * BM;

    const __half* ga = g_xq + (size_t)m0 * DIN;
    const __half* gb = g_wh + (size_t)n0 * DIN;

    auto load_stage = [&](int s, int k0) {
        const uint32_t abase = sbase + (uint32_t)s * STAGE_B;
        const uint32_t bbase = abase + (uint32_t)TILE_B;
        #pragma unroll
        for (int it = 0; it < 4; it++) {
            int c = tid + it * 256;          // 0..1023, one 16B chunk each
            int r = c >> 3;                  // row 0..127
            int colh = (c & 7) * 8;          // column in halves
            uint32_t soff = (uint32_t)(r * SROWB + colh * 2);
            cp_async16(abase + soff, ga + (size_t)r * DIN + k0 + colh);
            cp_async16(bbase + soff, gb + (size_t)r * DIN + k0 + colh);
        }
        asm volatile("cp.async.commit_group;" ::: "memory");
    };

    float acc[2][8][4];
    #pragma unroll
    for (int mi = 0; mi < 2; mi++)
        #pragma unroll
        for (int p = 0; p < 8; p++)
            #pragma unroll
            for (int j = 0; j < 4; j++)
                acc[mi][p][j] = 0.0f;

    load_stage(0, 0);
    load_stage(1, BK);

    // ldmatrix lane addressing: lanes 0-15 -> rows, lanes 16-31 -> +16B in k
    const uint32_t lrow = (uint32_t)(lane & 15);
    const uint32_t lkof = (uint32_t)((lane >> 4) * 16);   // bytes

    int sc = 0;
    for (int i = 0; i < KITERS; i++) {
        if (i + 2 < KITERS) cp_wait<1>(); else cp_wait<0>();
        __syncthreads();
        if (i + 2 < KITERS) {
            int sl = sc + 2; if (sl >= NSTAGES) sl -= NSTAGES;
            load_stage(sl, (i + 2) * BK);
        }

        const uint32_t abase = sbase + (uint32_t)sc * STAGE_B;
        const uint32_t bbase = abase + (uint32_t)TILE_B;
        const uint32_t arow0 = abase + (uint32_t)(warp_m * 32 + lrow) * SROWB + lkof;
        const uint32_t brow0 = bbase + (uint32_t)(warp_n * 64 + lrow) * SROWB + lkof;

        // Double-buffered fragments: load ka+1 while MMAs of ka execute.
        uint32_t a[2][2][4];
        uint32_t bq[2][4][4];

        // prime ka = 0
        ldsm_x4(a[0][0], arow0);
        ldsm_x4(a[0][1], arow0 + 16u * SROWB);
        #pragma unroll
        for (int t = 0; t < 4; t++)
            ldsm_x4(bq[0][t], brow0 + (uint32_t)(t * 16) * SROWB);

        #pragma unroll
        for (int ka = 0; ka < 4; ka++) {
            const int cur = ka & 1;
            const int nxt = cur ^ 1;
            if (ka < 3) {
                const uint32_t kb2 = (uint32_t)((ka + 1) * 32);
                ldsm_x4(a[nxt][0], arow0 + kb2);
                ldsm_x4(a[nxt][1], arow0 + 16u * SROWB + kb2);
                #pragma unroll
                for (int t = 0; t < 4; t++)
                    ldsm_x4(bq[nxt][t], brow0 + (uint32_t)(t * 16) * SROWB + kb2);
            }
            #pragma unroll
            for (int mi = 0; mi < 2; mi++) {
                #pragma unroll
                for (int t = 0; t < 4; t++) {
                    // x4 B load t covers n-atoms 2t (regs 0,2) and 2t+1 (1,3)
                    mma16816(acc[mi][2 * t],     a[cur][mi], bq[cur][t][0], bq[cur][t][2]);
                    mma16816(acc[mi][2 * t + 1], a[cur][mi], bq[cur][t][1], bq[cur][t][3]);
                }
            }
        }
        sc++; if (sc == NSTAGES) sc = 0;
    }

    // Epilogue: scale by per-token scale, store fp32.
    const int qrow = lane >> 2;          // 0..7
    const int qcol = (lane & 3) * 2;     // 0,2,4,6
    #pragma unroll
    for (int mi = 0; mi < 2; mi++) {
        const int mrow0 = m0 + warp_m * 32 + mi * 16 + qrow;
        const float sc0 = g_xscale[mrow0];
        const float sc1 = g_xscale[mrow0 + 8];
        float* o0 = out + (size_t)mrow0 * DOUT + n0 + warp_n * 64 + qcol;
        float* o1 = o0 + (size_t)8 * DOUT;
        #pragma unroll
        for (int p = 0; p < 8; p++) {
            *(float2*)(o0 + p * 8) = make_float2(sc0 * acc[mi][p][0],
                                                 sc0 * acc[mi][p][1]);
            *(float2*)(o1 + p * 8) = make_float2(sc1 * acc[mi][p][2],
                                                 sc1 * acc[mi][p][3]);
        }
    }
}

// ============================================================================
// Launch
// ============================================================================
extern "C" void kernel_launch(void* const* d_in, const int* in_sizes, int n_in,
                              void* d_out, int out_size) {
    (void)in_sizes; (void)n_in; (void)out_size;
    const float* x  = (const float*)d_in[0];
    const int*   wi = (const int*)d_in[1];
    const float* ws = (const float*)d_in[2];
    const float* wz = (const float*)d_in[3];
    float* out = (float*)d_out;

    cudaFuncSetAttribute(qgemm_kernel,
                         cudaFuncAttributeMaxDynamicSharedMemorySize, GEMM_SMEM);

    prep_kernel<<<MROWS + (DOUT * DIN) / 2048, 256>>>(x, wi, ws, wz);
    qgemm_kernel<<<dim3(DOUT / BN, MROWS / BM), 256, GEMM_SMEM>>>(out);
}